// round 15
// baseline (speedup 1.0000x reference)
#include <cuda_runtime.h>
#include <cstdint>

// Problem constants
#define B_SZ   8
#define T_SEQ  1024
#define C_DIM  768
#define H_NUM  12
#define D_DIM  64
#define M_ROWS (B_SZ * T_SEQ)          // 8192
#define N_QKV  (3 * C_DIM)             // 2304
#define LOG2E  1.4426950408889634f
#define SOFTMAX_SCALE2 (0.125f * LOG2E)   // 1/sqrt(64) * log2(e)

// Scratch (allocation-free rule: __device__ globals)
__device__ float g_qkv[(size_t)M_ROWS * N_QKV];   // [8192, 2304] (tf32-rounded)
__device__ float g_y[(size_t)M_ROWS * C_DIM];     // [8192, 768] (tf32-rounded)
__device__ float g_xr[(size_t)M_ROWS * C_DIM];    // tf32-rounded x
__device__ float g_War[(size_t)C_DIM * N_QKV];    // tf32-rounded W_attn
__device__ float g_Wpr[(size_t)C_DIM * C_DIM];    // tf32-rounded W_proj

// ---------------------------------------------------------------------------
// TF32 helpers
// ---------------------------------------------------------------------------
__device__ __forceinline__ uint32_t f2tf32(float x) {
    uint32_t r;
    asm("cvt.rna.tf32.f32 %0, %1;" : "=r"(r) : "f"(x));
    return r;
}

__device__ __forceinline__ void mma_tf32(float c[4],
                                         uint32_t a0, uint32_t a1,
                                         uint32_t a2, uint32_t a3,
                                         uint32_t b0, uint32_t b1) {
    asm volatile(
        "mma.sync.aligned.m16n8k8.row.col.f32.tf32.tf32.f32 "
        "{%0,%1,%2,%3}, {%4,%5,%6,%7}, {%8,%9}, {%0,%1,%2,%3};\n"
        : "+f"(c[0]), "+f"(c[1]), "+f"(c[2]), "+f"(c[3])
        : "r"(a0), "r"(a1), "r"(a2), "r"(a3), "r"(b0), "r"(b1));
}

__device__ __forceinline__ void cp_async16(uint32_t saddr, const void* gptr) {
    asm volatile("cp.async.cg.shared.global [%0], [%1], 16;\n"
                 :: "r"(saddr), "l"(gptr));
}
__device__ __forceinline__ void cp_commit() {
    asm volatile("cp.async.commit_group;\n");
}
template <int N>
__device__ __forceinline__ void cp_wait() {
    asm volatile("cp.async.wait_group %0;\n" :: "n"(N));
}

// ---------------------------------------------------------------------------
// Elementwise tf32 RNA pre-rounding
// ---------------------------------------------------------------------------
__global__ void round_tf32_kernel(const float* __restrict__ src,
                                  float* __restrict__ dst, int n4)
{
    const int i = blockIdx.x * blockDim.x + threadIdx.x;
    if (i < n4) {
        float4 v = *(const float4*)(src + (size_t)i * 4);
        uint4 r;
        r.x = f2tf32(v.x); r.y = f2tf32(v.y);
        r.z = f2tf32(v.z); r.w = f2tf32(v.w);
        *(uint4*)(dst + (size_t)i * 4) = r;
    }
}

// ---------------------------------------------------------------------------
// TF32 tensor-core GEMM with bias. BM=BN=128, BK=32 (was 16): one barrier
// per 2x the MMA work -> fewer pipeline bubbles at stage boundaries.
// 128 threads (4 warps 2x2), warp tile 64x64, 3-stage cp.async pipeline.
// smem/stage: A [128][36] words ([m][k], bank = 4g+t -> conflict-free),
//             B [32][136] words ([k][n], conflict-free as before).
// ROUND_OUT: round the stored C to tf32 (for qkv feeding attention).
// ---------------------------------------------------------------------------
#define SA 36
#define SB 136
#define GA_W  (128 * SA)               // 4608 words
#define GB_W  (32 * SB)                // 4352 words
#define GEMM_SMEM_BYTES (3 * (GA_W + GB_W) * 4)   // 107520

template <bool ROUND_OUT>
__global__ __launch_bounds__(128, 2)
void gemm_tf32_bias_kernel(const float* __restrict__ A,
                           const float* __restrict__ B,
                           const float* __restrict__ bias,
                           float* __restrict__ C,
                           int M, int N, int K)
{
    constexpr int BM = 128, BN = 128, BK = 32;

    extern __shared__ uint32_t smg[];

    const int tid  = threadIdx.x;            // 0..127
    const int brow = blockIdx.y;
    const int bcol = blockIdx.x;

    const int warp = tid >> 5;               // 0..3
    const int lane = tid & 31;
    const int g    = lane >> 2;              // 0..7
    const int t    = lane & 3;               // 0..3
    const int wm   = (warp & 1) * 64;
    const int wn   = (warp >> 1) * 64;

    const float* Ablk = A + (size_t)brow * BM * K;
    const float* Bblk = B + (size_t)bcol * BN;

    // cp.async mappings (BK=32):
    // A: 128 rows x 32 words = 2048 chunks/2? -> 1024 x 16B chunks, 8/thread:
    //    4 lanes per row, rows tid>>2 (+0,+32,+64,+96), col halves +0 / +16.
    const int a_row = tid >> 2;              // 0..31
    const int a_col = (tid & 3) * 4;         // 0,4,8,12
    // B: 32 rows x 128 words = 1024 chunks, 8/thread:
    //    rows tid>>5 (+0,+4,...,+28), full coalesced rows.
    const int b_row = tid >> 5;              // 0..3
    const int b_col = (tid & 31) * 4;        // 0..124

    uint32_t sbase;
    {
        void* p = (void*)smg;
        sbase = (uint32_t)__cvta_generic_to_shared(p);
    }

    const int ntiles = K / BK;               // 24

    auto issue_stage = [&](int tile, int stage) {
        const uint32_t as = sbase + (uint32_t)(stage * (GA_W + GB_W)) * 4;
        const uint32_t bs = as + GA_W * 4;
        const int k0 = tile * BK;
        #pragma unroll
        for (int rb = 0; rb < 4; rb++) {
            const int m = a_row + rb * 32;
            cp_async16(as + (uint32_t)(m * SA + a_col) * 4,
                       Ablk + (size_t)m * K + k0 + a_col);
            cp_async16(as + (uint32_t)(m * SA + a_col + 16) * 4,
                       Ablk + (size_t)m * K + k0 + a_col + 16);
        }
        #pragma unroll
        for (int rb = 0; rb < 8; rb++) {
            const int kr = b_row + rb * 4;
            cp_async16(bs + (uint32_t)(kr * SB + b_col) * 4,
                       Bblk + (size_t)(k0 + kr) * N + b_col);
        }
        cp_commit();
    };

    float acc[4][8][4];                      // [mt][nt][frag]
    #pragma unroll
    for (int mt = 0; mt < 4; mt++)
        #pragma unroll
        for (int nt = 0; nt < 8; nt++)
            #pragma unroll
            for (int i = 0; i < 4; i++)
                acc[mt][nt][i] = 0.0f;

    issue_stage(0, 0);
    issue_stage(1, 1);

    int stage = 0;
    for (int i = 0; i < ntiles; i++) {
        if (i + 1 < ntiles) cp_wait<1>(); else cp_wait<0>();
        __syncthreads();

        const uint32_t* As = smg + stage * (GA_W + GB_W);   // [m][SA]
        const uint32_t* Bs = As + GA_W;                     // [k][SB]

        #pragma unroll
        for (int ks = 0; ks < BK; ks += 8) {
            uint32_t a[4][4], bf[8][2];
            #pragma unroll
            for (int mt = 0; mt < 4; mt++) {
                const int m = wm + mt * 16 + g;
                a[mt][0] = As[m * SA + ks + t];
                a[mt][1] = As[(m + 8) * SA + ks + t];
                a[mt][2] = As[m * SA + ks + t + 4];
                a[mt][3] = As[(m + 8) * SA + ks + t + 4];
            }
            #pragma unroll
            for (int nt = 0; nt < 8; nt++) {
                const int n = wn + nt * 8 + g;
                bf[nt][0] = Bs[(ks + t) * SB + n];
                bf[nt][1] = Bs[(ks + t + 4) * SB + n];
            }
            #pragma unroll
            for (int mt = 0; mt < 4; mt++)
                #pragma unroll
                for (int nt = 0; nt < 8; nt++)
                    mma_tf32(acc[mt][nt],
                             a[mt][0], a[mt][1], a[mt][2], a[mt][3],
                             bf[nt][0], bf[nt][1]);
        }

        if (i + 2 < ntiles) issue_stage(i + 2, (stage + 2) % 3);
        stage = (stage + 1) % 3;
    }

    // Epilogue: bias + store (optionally tf32-rounded)
    #pragma unroll
    for (int mt = 0; mt < 4; mt++) {
        const size_t row0 = (size_t)brow * BM + wm + mt * 16 + g;
        #pragma unroll
        for (int nt = 0; nt < 8; nt++) {
            const int col = bcol * BN + wn + nt * 8 + 2 * t;
            const float bx = bias[col];
            const float by = bias[col + 1];
            float r0 = acc[mt][nt][0] + bx, r1 = acc[mt][nt][1] + by;
            float r2 = acc[mt][nt][2] + bx, r3 = acc[mt][nt][3] + by;
            if (ROUND_OUT) {
                r0 = __uint_as_float(f2tf32(r0));
                r1 = __uint_as_float(f2tf32(r1));
                r2 = __uint_as_float(f2tf32(r2));
                r3 = __uint_as_float(f2tf32(r3));
            }
            *(float2*)(C + row0 * N + col)       = make_float2(r0, r1);
            *(float2*)(C + (row0 + 8) * N + col) = make_float2(r2, r3);
        }
    }
}

// ---------------------------------------------------------------------------
// Tensor-core causal flash attention (TF32 m16n8k8). Unchanged from R14:
// 3 CTAs/SM, raw float4 K/V copies (qkv pre-rounded), log2-domain softmax.
// ---------------------------------------------------------------------------
#define SQ 68
#define SV 72
#define ATT_SMEM_BYTES ((64 * SQ * 3 + 64 * SV) * 4)   // 70656

__global__ __launch_bounds__(128)
void attn_mma_kernel(const float* __restrict__ qkv, float* __restrict__ y)
{
    extern __shared__ uint32_t sm[];
    uint32_t* Qs = sm;                   // [64][SQ]
    uint32_t* Ks = Qs + 64 * SQ;         // [64][SQ]
    uint32_t* Vs = Ks + 64 * SQ;         // [64][SV]
    uint32_t* Ps = Vs + 64 * SV;         // [64][SQ]

    const int bh    = blockIdx.y;                    // 0..95
    const int b     = bh / H_NUM;
    const int h     = bh % H_NUM;
    const int qtile = (gridDim.x - 1) - blockIdx.x;  // heavy tiles first
    const int tid   = threadIdx.x;
    const int warp  = tid >> 5;
    const int lane  = tid & 31;
    const int g     = lane >> 2;                     // 0..7
    const int t     = lane & 3;                      // 0..3
    const int q0    = qtile * 64;

    const float* base = qkv + (size_t)b * T_SEQ * N_QKV + h * D_DIM;

    // Load Q tile, scaled by 1/sqrt(D)*log2e then rounded to tf32
    for (int idx = tid; idx < 64 * 16; idx += 128) {
        const int r  = idx >> 4;
        const int c4 = (idx & 15) * 4;
        float4 v = *(const float4*)(base + (size_t)(q0 + r) * N_QKV + c4);
        Qs[r * SQ + c4 + 0] = f2tf32(v.x * SOFTMAX_SCALE2);
        Qs[r * SQ + c4 + 1] = f2tf32(v.y * SOFTMAX_SCALE2);
        Qs[r * SQ + c4 + 2] = f2tf32(v.z * SOFTMAX_SCALE2);
        Qs[r * SQ + c4 + 3] = f2tf32(v.w * SOFTMAX_SCALE2);
    }

    const int qr = warp * 16;       // warp's first local q row
    const int qa = q0 + qr + g;     // global query row (fragment row 0)
    const int qb = qa + 8;          // global query row (fragment row 1)

    float m0 = -1e30f, m1 = -1e30f, l0 = 0.0f, l1 = 0.0f;
    float O[8][4];
    #pragma unroll
    for (int n = 0; n < 8; n++)
        #pragma unroll
        for (int i = 0; i < 4; i++)
            O[n][i] = 0.0f;

    for (int kt = 0; kt <= qtile; kt++) {
        __syncthreads();
        // K/V tile fill: raw float4 copy (values already tf32-rounded)
        const float* kbase = base + (size_t)kt * 64 * N_QKV;
        for (int idx = tid; idx < 64 * 16; idx += 128) {
            const int r  = idx >> 4;
            const int c4 = (idx & 15) * 4;
            uint4 kv = *(const uint4*)(kbase + (size_t)r * N_QKV + C_DIM + c4);
            uint4 vv = *(const uint4*)(kbase + (size_t)r * N_QKV + 2 * C_DIM + c4);
            *(uint4*)&Ks[r * SQ + c4] = kv;
            *(uint4*)&Vs[r * SV + c4] = vv;
        }
        __syncthreads();

        // S = Q * K^T
        float s[8][4];
        #pragma unroll
        for (int n = 0; n < 8; n++)
            #pragma unroll
            for (int i = 0; i < 4; i++)
                s[n][i] = 0.0f;

        #pragma unroll
        for (int ks = 0; ks < 8; ks++) {
            const uint32_t a0 = Qs[(qr + g)     * SQ + ks * 8 + t];
            const uint32_t a1 = Qs[(qr + g + 8) * SQ + ks * 8 + t];
            const uint32_t a2 = Qs[(qr + g)     * SQ + ks * 8 + t + 4];
            const uint32_t a3 = Qs[(qr + g + 8) * SQ + ks * 8 + t + 4];
            #pragma unroll
            for (int nt = 0; nt < 8; nt++) {
                const uint32_t b0 = Ks[(nt * 8 + g) * SQ + ks * 8 + t];
                const uint32_t b1 = Ks[(nt * 8 + g) * SQ + ks * 8 + t + 4];
                mma_tf32(s[nt], a0, a1, a2, a3, b0, b1);
            }
        }

        // Causal mask (only the diagonal tile)
        if (kt == qtile) {
            #pragma unroll
            for (int nt = 0; nt < 8; nt++) {
                const int kc = kt * 64 + nt * 8 + 2 * t;
                if (kc     > qa) s[nt][0] = -1e30f;
                if (kc + 1 > qa) s[nt][1] = -1e30f;
                if (kc     > qb) s[nt][2] = -1e30f;
                if (kc + 1 > qb) s[nt][3] = -1e30f;
            }
        }

        // Online softmax (log2 domain)
        float mc0 = -1e30f, mc1 = -1e30f;
        #pragma unroll
        for (int nt = 0; nt < 8; nt++) {
            mc0 = fmaxf(mc0, fmaxf(s[nt][0], s[nt][1]));
            mc1 = fmaxf(mc1, fmaxf(s[nt][2], s[nt][3]));
        }
        mc0 = fmaxf(mc0, __shfl_xor_sync(0xffffffffu, mc0, 1));
        mc0 = fmaxf(mc0, __shfl_xor_sync(0xffffffffu, mc0, 2));
        mc1 = fmaxf(mc1, __shfl_xor_sync(0xffffffffu, mc1, 1));
        mc1 = fmaxf(mc1, __shfl_xor_sync(0xffffffffu, mc1, 2));

        const float mn0 = fmaxf(m0, mc0);
        const float mn1 = fmaxf(m1, mc1);
        const float cr0 = exp2f(m0 - mn0);
        const float cr1 = exp2f(m1 - mn1);
        m0 = mn0; m1 = mn1;

        float pl0 = 0.0f, pl1 = 0.0f;
        #pragma unroll
        for (int nt = 0; nt < 8; nt++) {
            const float p0 = exp2f(s[nt][0] - m0);
            const float p1 = exp2f(s[nt][1] - m0);
            const float p2 = exp2f(s[nt][2] - m1);
            const float p3 = exp2f(s[nt][3] - m1);
            pl0 += p0 + p1;
            pl1 += p2 + p3;
            const int col = nt * 8 + 2 * t;
            Ps[(qr + g)     * SQ + col]     = f2tf32(p0);
            Ps[(qr + g)     * SQ + col + 1] = f2tf32(p1);
            Ps[(qr + g + 8) * SQ + col]     = f2tf32(p2);
            Ps[(qr + g + 8) * SQ + col + 1] = f2tf32(p3);
        }
        pl0 += __shfl_xor_sync(0xffffffffu, pl0, 1);
        pl0 += __shfl_xor_sync(0xffffffffu, pl0, 2);
        pl1 += __shfl_xor_sync(0xffffffffu, pl1, 1);
        pl1 += __shfl_xor_sync(0xffffffffu, pl1, 2);

        l0 = l0 * cr0 + pl0;
        l1 = l1 * cr1 + pl1;
        #pragma unroll
        for (int n = 0; n < 8; n++) {
            O[n][0] *= cr0; O[n][1] *= cr0;
            O[n][2] *= cr1; O[n][3] *= cr1;
        }
        __syncwarp();   // P rows are warp-private; quad cross-reads below

        // O += P * V
        #pragma unroll
        for (int ks = 0; ks < 8; ks++) {
            const uint32_t a0 = Ps[(qr + g)     * SQ + ks * 8 + t];
            const uint32_t a1 = Ps[(qr + g + 8) * SQ + ks * 8 + t];
            const uint32_t a2 = Ps[(qr + g)     * SQ + ks * 8 + t + 4];
            const uint32_t a3 = Ps[(qr + g + 8) * SQ + ks * 8 + t + 4];
            #pragma unroll
            for (int nt2 = 0; nt2 < 8; nt2++) {
                const uint32_t b0 = Vs[(ks * 8 + t)     * SV + nt2 * 8 + g];
                const uint32_t b1 = Vs[(ks * 8 + t + 4) * SV + nt2 * 8 + g];
                mma_tf32(O[nt2], a0, a1, a2, a3, b0, b1);
            }
        }
    }

    // Epilogue: normalize, tf32-round (proj GEMM input), and store
    const float i0 = 1.0f / l0;
    const float i1 = 1.0f / l1;
    float* ya = y + ((size_t)b * T_SEQ + qa) * C_DIM + h * D_DIM;
    float* yb = y + ((size_t)b * T_SEQ + qb) * C_DIM + h * D_DIM;
    #pragma unroll
    for (int nt2 = 0; nt2 < 8; nt2++) {
        const int d = nt2 * 8 + 2 * t;
        *(float2*)(ya + d) = make_float2(
            __uint_as_float(f2tf32(O[nt2][0] * i0)),
            __uint_as_float(f2tf32(O[nt2][1] * i0)));
        *(float2*)(yb + d) = make_float2(
            __uint_as_float(f2tf32(O[nt2][2] * i1)),
            __uint_as_float(f2tf32(O[nt2][3] * i1)));
    }
}

// ---------------------------------------------------------------------------
// Launch
// ---------------------------------------------------------------------------
extern "C" void kernel_launch(void* const* d_in, const int* in_sizes, int n_in,
                              void* d_out, int out_size)
{
    const float* x      = (const float*)d_in[0];   // [8, 1024, 768]
    const float* W_attn = (const float*)d_in[1];   // [768, 2304]
    const float* b_attn = (const float*)d_in[2];   // [2304]
    const float* W_proj = (const float*)d_in[3];   // [768, 768]
    const float* b_proj = (const float*)d_in[4];   // [768]
    float* out = (float*)d_out;                    // [8, 1024, 768]

    float* qkv;  cudaGetSymbolAddress((void**)&qkv, g_qkv);
    float* ybuf; cudaGetSymbolAddress((void**)&ybuf, g_y);
    float* xr;   cudaGetSymbolAddress((void**)&xr,  g_xr);
    float* War;  cudaGetSymbolAddress((void**)&War, g_War);
    float* Wpr;  cudaGetSymbolAddress((void**)&Wpr, g_Wpr);

    cudaFuncSetAttribute(attn_mma_kernel,
                         cudaFuncAttributeMaxDynamicSharedMemorySize,
                         ATT_SMEM_BYTES);
    cudaFuncSetAttribute(gemm_tf32_bias_kernel<true>,
                         cudaFuncAttributeMaxDynamicSharedMemorySize,
                         GEMM_SMEM_BYTES);
    cudaFuncSetAttribute(gemm_tf32_bias_kernel<false>,
                         cudaFuncAttributeMaxDynamicSharedMemorySize,
                         GEMM_SMEM_BYTES);

    // 0) Pre-round inputs to tf32 (RNA)
    {
        const int nx = M_ROWS * C_DIM / 4;
        const int na = C_DIM * N_QKV / 4;
        const int np = C_DIM * C_DIM / 4;
        round_tf32_kernel<<<(nx + 255) / 256, 256>>>(x, xr, nx);
        round_tf32_kernel<<<(na + 255) / 256, 256>>>(W_attn, War, na);
        round_tf32_kernel<<<(np + 255) / 256, 256>>>(W_proj, Wpr, np);
    }
    // 1) QKV GEMM (BK=32 pipeline; output tf32-rounded for attention)
    {
        dim3 grid(N_QKV / 128, M_ROWS / 128);   // (18, 64)
        gemm_tf32_bias_kernel<true><<<grid, 128, GEMM_SMEM_BYTES>>>(
            xr, War, b_attn, qkv, M_ROWS, N_QKV, C_DIM);
    }
    // 2) Causal flash attention (unchanged R14 structure)
    {
        dim3 grid(T_SEQ / 64, B_SZ * H_NUM);    // (16, 96)
        attn_mma_kernel<<<grid, 128, ATT_SMEM_BYTES>>>(qkv, ybuf);
    }
    // 3) Projection GEMM (BK=32 pipeline, full-fp32 output)
    {
        dim3 grid(C_DIM / 128, M_ROWS / 128);   // (6, 64)
        gemm_tf32_bias_kernel<false><<<grid, 128, GEMM_SMEM_BYTES>>>(
            ybuf, Wpr, b_proj, out, M_ROWS, C_DIM, C_DIM);
    }
}

// round 16
// speedup vs baseline: 1.1024x; 1.1024x over previous
#include <cuda_runtime.h>
#include <cstdint>

// Problem constants
#define B_SZ   8
#define T_SEQ  1024
#define C_DIM  768
#define H_NUM  12
#define D_DIM  64
#define M_ROWS (B_SZ * T_SEQ)          // 8192
#define N_QKV  (3 * C_DIM)             // 2304
#define LOG2E  1.4426950408889634f
#define SOFTMAX_SCALE2 (0.125f * LOG2E)   // 1/sqrt(64) * log2(e)

// Scratch (allocation-free rule: __device__ globals)
__device__ float g_qkv[(size_t)M_ROWS * N_QKV];   // [8192, 2304] (tf32-rounded)
__device__ float g_y[(size_t)M_ROWS * C_DIM];     // [8192, 768] (tf32-rounded)
__device__ float g_xr[(size_t)M_ROWS * C_DIM];    // tf32-rounded x [m][k]
__device__ float g_WarT[(size_t)N_QKV * C_DIM];   // tf32-rounded W_attn^T [N][K]
__device__ float g_WprT[(size_t)C_DIM * C_DIM];   // tf32-rounded W_proj^T [N][K]

// ---------------------------------------------------------------------------
// TF32 / MMA / copy helpers
// ---------------------------------------------------------------------------
__device__ __forceinline__ uint32_t f2tf32(float x) {
    uint32_t r;
    asm("cvt.rna.tf32.f32 %0, %1;" : "=r"(r) : "f"(x));
    return r;
}

__device__ __forceinline__ void mma_tf32(float c[4],
                                         uint32_t a0, uint32_t a1,
                                         uint32_t a2, uint32_t a3,
                                         uint32_t b0, uint32_t b1) {
    asm volatile(
        "mma.sync.aligned.m16n8k8.row.col.f32.tf32.tf32.f32 "
        "{%0,%1,%2,%3}, {%4,%5,%6,%7}, {%8,%9}, {%0,%1,%2,%3};\n"
        : "+f"(c[0]), "+f"(c[1]), "+f"(c[2]), "+f"(c[3])
        : "r"(a0), "r"(a1), "r"(a2), "r"(a3), "r"(b0), "r"(b1));
}

__device__ __forceinline__ void ldmatrix_x4(uint32_t& r0, uint32_t& r1,
                                            uint32_t& r2, uint32_t& r3,
                                            uint32_t saddr) {
    asm volatile("ldmatrix.sync.aligned.m8n8.x4.shared.b16 {%0,%1,%2,%3}, [%4];"
                 : "=r"(r0), "=r"(r1), "=r"(r2), "=r"(r3) : "r"(saddr));
}

__device__ __forceinline__ void cp_async16(uint32_t saddr, const void* gptr) {
    asm volatile("cp.async.cg.shared.global [%0], [%1], 16;\n"
                 :: "r"(saddr), "l"(gptr));
}
__device__ __forceinline__ void cp_commit() {
    asm volatile("cp.async.commit_group;\n");
}
template <int N>
__device__ __forceinline__ void cp_wait() {
    asm volatile("cp.async.wait_group %0;\n" :: "n"(N));
}

// ---------------------------------------------------------------------------
// Pre-pass kernels: tf32 rounding (linear) and rounding+transpose (weights)
// ---------------------------------------------------------------------------
__global__ void round_tf32_kernel(const float* __restrict__ src,
                                  float* __restrict__ dst, int n4)
{
    const int i = blockIdx.x * blockDim.x + threadIdx.x;
    if (i < n4) {
        float4 v = *(const float4*)(src + (size_t)i * 4);
        uint4 r;
        r.x = f2tf32(v.x); r.y = f2tf32(v.y);
        r.z = f2tf32(v.z); r.w = f2tf32(v.w);
        *(uint4*)(dst + (size_t)i * 4) = r;
    }
}

// src[K][N] row-major -> dst[N][K] row-major, tf32-rounded. 32x32 smem tiles.
__global__ void round_transpose_tf32_kernel(const float* __restrict__ src,
                                            float* __restrict__ dst,
                                            int K, int N)
{
    __shared__ uint32_t tile[32][33];
    const int n0 = blockIdx.x * 32;
    const int k0 = blockIdx.y * 32;
    const int tx = threadIdx.x;        // 0..31
    const int ty = threadIdx.y;        // 0..7
    #pragma unroll
    for (int i = ty; i < 32; i += 8)
        tile[i][tx] = f2tf32(src[(size_t)(k0 + i) * N + n0 + tx]);
    __syncthreads();
    #pragma unroll
    for (int i = ty; i < 32; i += 8)
        dst[(size_t)(n0 + i) * K + k0 + tx] =
            __uint_as_float(tile[tx][i]);
}

// ---------------------------------------------------------------------------
// TF32 tensor-core GEMM with bias: C[M,N] = A[M,K] * Bt[N,K]^T + bias[N]
// Both operands [outer][k] row-major -> symmetric cp.async + ldmatrix loads.
// BM=BN=128, BK=16, 128 threads (4 warps 2x2), warp tile 64x64.
// Per k-step: 8 ldmatrix.x4 + 32 MMA (was 32 LDS + 32 MMA) -> tensor-bound.
// 3-stage cp.async pipeline, one __syncthreads per K-tile.
// smem/stage: A [128][20] + Bt [128][20] words; ldmatrix phases conflict-free.
// ROUND_OUT: round the stored C to tf32 (for qkv feeding attention).
// ---------------------------------------------------------------------------
#define SA 20
#define GA_W  (128 * SA)               // 2560 words
#define GB_W  (128 * SA)               // 2560 words
#define GEMM_SMEM_BYTES (3 * (GA_W + GB_W) * 4)   // 61440

template <bool ROUND_OUT>
__global__ __launch_bounds__(128, 2)
void gemm_tf32_bias_kernel(const float* __restrict__ A,
                           const float* __restrict__ Bt,
                           const float* __restrict__ bias,
                           float* __restrict__ C,
                           int M, int N, int K)
{
    constexpr int BM = 128, BN = 128, BK = 16;

    extern __shared__ uint32_t smg[];

    const int tid  = threadIdx.x;            // 0..127
    const int brow = blockIdx.y;
    const int bcol = blockIdx.x;

    const int warp = tid >> 5;               // 0..3
    const int lane = tid & 31;
    const int g    = lane >> 2;              // 0..7
    const int t    = lane & 3;               // 0..3
    const int q    = lane >> 3;              // ldmatrix tile index 0..3
    const int r    = lane & 7;               // ldmatrix row-in-tile 0..7
    const int wm   = (warp & 1) * 64;
    const int wn   = (warp >> 1) * 64;

    const float* Ablk = A  + (size_t)brow * BM * K;
    const float* Bblk = Bt + (size_t)bcol * BN * K;

    // cp.async mapping (identical for A and Bt): 128 rows x 16 words,
    // 512 chunks of 16B, 4 per thread (rows +0,+32,+64,+96).
    const int ld_row = tid >> 2;             // 0..31
    const int ld_col = (tid & 3) * 4;        // 0,4,8,12

    uint32_t sbase;
    {
        void* p = (void*)smg;
        sbase = (uint32_t)__cvta_generic_to_shared(p);
    }

    const int ntiles = K / BK;               // 48

    auto issue_stage = [&](int tile, int stage) {
        const uint32_t as = sbase + (uint32_t)(stage * (GA_W + GB_W)) * 4;
        const uint32_t bs = as + GA_W * 4;
        const int k0 = tile * BK;
        #pragma unroll
        for (int rb = 0; rb < 4; rb++) {
            const int m = ld_row + rb * 32;
            cp_async16(as + (uint32_t)(m * SA + ld_col) * 4,
                       Ablk + (size_t)m * K + k0 + ld_col);
            cp_async16(bs + (uint32_t)(m * SA + ld_col) * 4,
                       Bblk + (size_t)m * K + k0 + ld_col);
        }
        cp_commit();
    };

    // ldmatrix per-lane row/col offsets (stage-relative, words)
    // A tiles for mt: rows wm+mt*16+(q&1)*8+r, col (q>>1)*4
    // B tiles for j:  rows wn+j*16+(q>>1)*8+r, col (q&1)*4
    const uint32_t a_off = (uint32_t)(((q & 1) * 8 + r) * SA + (q >> 1) * 4) * 4;
    const uint32_t b_off = (uint32_t)(((q >> 1) * 8 + r) * SA + (q & 1) * 4) * 4;

    float acc[4][8][4];                      // [mt][nt][frag]
    #pragma unroll
    for (int mt = 0; mt < 4; mt++)
        #pragma unroll
        for (int nt = 0; nt < 8; nt++)
            #pragma unroll
            for (int i = 0; i < 4; i++)
                acc[mt][nt][i] = 0.0f;

    issue_stage(0, 0);
    issue_stage(1, 1);

    int stage = 0;
    for (int i = 0; i < ntiles; i++) {
        if (i + 1 < ntiles) cp_wait<1>(); else cp_wait<0>();
        __syncthreads();

        const uint32_t as = sbase + (uint32_t)(stage * (GA_W + GB_W)) * 4;
        const uint32_t bs = as + GA_W * 4;
        const uint32_t a_base = as + (uint32_t)(wm * SA) * 4 + a_off;
        const uint32_t b_base = bs + (uint32_t)(wn * SA) * 4 + b_off;

        #pragma unroll
        for (int ks = 0; ks < BK; ks += 8) {
            uint32_t a[4][4], bf[8][2];
            #pragma unroll
            for (int mt = 0; mt < 4; mt++)
                ldmatrix_x4(a[mt][0], a[mt][1], a[mt][2], a[mt][3],
                            a_base + (uint32_t)(mt * 16 * SA + ks) * 4);
            #pragma unroll
            for (int j = 0; j < 4; j++)
                ldmatrix_x4(bf[2*j][0], bf[2*j][1], bf[2*j+1][0], bf[2*j+1][1],
                            b_base + (uint32_t)(j * 16 * SA + ks) * 4);
            #pragma unroll
            for (int mt = 0; mt < 4; mt++)
                #pragma unroll
                for (int nt = 0; nt < 8; nt++)
                    mma_tf32(acc[mt][nt],
                             a[mt][0], a[mt][1], a[mt][2], a[mt][3],
                             bf[nt][0], bf[nt][1]);
        }

        if (i + 2 < ntiles) issue_stage(i + 2, (stage + 2) % 3);
        stage = (stage + 1) % 3;
    }

    // Epilogue: bias + store (optionally tf32-rounded)
    #pragma unroll
    for (int mt = 0; mt < 4; mt++) {
        const size_t row0 = (size_t)brow * BM + wm + mt * 16 + g;
        #pragma unroll
        for (int nt = 0; nt < 8; nt++) {
            const int col = bcol * BN + wn + nt * 8 + 2 * t;
            const float bx = bias[col];
            const float by = bias[col + 1];
            float r0 = acc[mt][nt][0] + bx, r1 = acc[mt][nt][1] + by;
            float r2 = acc[mt][nt][2] + bx, r3 = acc[mt][nt][3] + by;
            if (ROUND_OUT) {
                r0 = __uint_as_float(f2tf32(r0));
                r1 = __uint_as_float(f2tf32(r1));
                r2 = __uint_as_float(f2tf32(r2));
                r3 = __uint_as_float(f2tf32(r3));
            }
            *(float2*)(C + row0 * N + col)       = make_float2(r0, r1);
            *(float2*)(C + (row0 + 8) * N + col) = make_float2(r2, r3);
        }
    }
}

// ---------------------------------------------------------------------------
// Tensor-core causal flash attention (TF32 m16n8k8). Unchanged from R14:
// 3 CTAs/SM, raw float4 K/V copies (qkv pre-rounded), log2-domain softmax.
// ---------------------------------------------------------------------------
#define SQ 68
#define SV 72
#define ATT_SMEM_BYTES ((64 * SQ * 3 + 64 * SV) * 4)   // 70656

__global__ __launch_bounds__(128)
void attn_mma_kernel(const float* __restrict__ qkv, float* __restrict__ y)
{
    extern __shared__ uint32_t sm[];
    uint32_t* Qs = sm;                   // [64][SQ]
    uint32_t* Ks = Qs + 64 * SQ;         // [64][SQ]
    uint32_t* Vs = Ks + 64 * SQ;         // [64][SV]
    uint32_t* Ps = Vs + 64 * SV;         // [64][SQ]

    const int bh    = blockIdx.y;                    // 0..95
    const int b     = bh / H_NUM;
    const int h     = bh % H_NUM;
    const int qtile = (gridDim.x - 1) - blockIdx.x;  // heavy tiles first
    const int tid   = threadIdx.x;
    const int warp  = tid >> 5;
    const int lane  = tid & 31;
    const int g     = lane >> 2;                     // 0..7
    const int t     = lane & 3;                      // 0..3
    const int q0    = qtile * 64;

    const float* base = qkv + (size_t)b * T_SEQ * N_QKV + h * D_DIM;

    // Load Q tile, scaled by 1/sqrt(D)*log2e then rounded to tf32
    for (int idx = tid; idx < 64 * 16; idx += 128) {
        const int r  = idx >> 4;
        const int c4 = (idx & 15) * 4;
        float4 v = *(const float4*)(base + (size_t)(q0 + r) * N_QKV + c4);
        Qs[r * SQ + c4 + 0] = f2tf32(v.x * SOFTMAX_SCALE2);
        Qs[r * SQ + c4 + 1] = f2tf32(v.y * SOFTMAX_SCALE2);
        Qs[r * SQ + c4 + 2] = f2tf32(v.z * SOFTMAX_SCALE2);
        Qs[r * SQ + c4 + 3] = f2tf32(v.w * SOFTMAX_SCALE2);
    }

    const int qr = warp * 16;       // warp's first local q row
    const int qa = q0 + qr + g;     // global query row (fragment row 0)
    const int qb = qa + 8;          // global query row (fragment row 1)

    float m0 = -1e30f, m1 = -1e30f, l0 = 0.0f, l1 = 0.0f;
    float O[8][4];
    #pragma unroll
    for (int n = 0; n < 8; n++)
        #pragma unroll
        for (int i = 0; i < 4; i++)
            O[n][i] = 0.0f;

    for (int kt = 0; kt <= qtile; kt++) {
        __syncthreads();
        // K/V tile fill: raw float4 copy (values already tf32-rounded)
        const float* kbase = base + (size_t)kt * 64 * N_QKV;
        for (int idx = tid; idx < 64 * 16; idx += 128) {
            const int r  = idx >> 4;
            const int c4 = (idx & 15) * 4;
            uint4 kv = *(const uint4*)(kbase + (size_t)r * N_QKV + C_DIM + c4);
            uint4 vv = *(const uint4*)(kbase + (size_t)r * N_QKV + 2 * C_DIM + c4);
            *(uint4*)&Ks[r * SQ + c4] = kv;
            *(uint4*)&Vs[r * SV + c4] = vv;
        }
        __syncthreads();

        // S = Q * K^T
        float s[8][4];
        #pragma unroll
        for (int n = 0; n < 8; n++)
            #pragma unroll
            for (int i = 0; i < 4; i++)
                s[n][i] = 0.0f;

        #pragma unroll
        for (int ks = 0; ks < 8; ks++) {
            const uint32_t a0 = Qs[(qr + g)     * SQ + ks * 8 + t];
            const uint32_t a1 = Qs[(qr + g + 8) * SQ + ks * 8 + t];
            const uint32_t a2 = Qs[(qr + g)     * SQ + ks * 8 + t + 4];
            const uint32_t a3 = Qs[(qr + g + 8) * SQ + ks * 8 + t + 4];
            #pragma unroll
            for (int nt = 0; nt < 8; nt++) {
                const uint32_t b0 = Ks[(nt * 8 + g) * SQ + ks * 8 + t];
                const uint32_t b1 = Ks[(nt * 8 + g) * SQ + ks * 8 + t + 4];
                mma_tf32(s[nt], a0, a1, a2, a3, b0, b1);
            }
        }

        // Causal mask (only the diagonal tile)
        if (kt == qtile) {
            #pragma unroll
            for (int nt = 0; nt < 8; nt++) {
                const int kc = kt * 64 + nt * 8 + 2 * t;
                if (kc     > qa) s[nt][0] = -1e30f;
                if (kc + 1 > qa) s[nt][1] = -1e30f;
                if (kc     > qb) s[nt][2] = -1e30f;
                if (kc + 1 > qb) s[nt][3] = -1e30f;
            }
        }

        // Online softmax (log2 domain)
        float mc0 = -1e30f, mc1 = -1e30f;
        #pragma unroll
        for (int nt = 0; nt < 8; nt++) {
            mc0 = fmaxf(mc0, fmaxf(s[nt][0], s[nt][1]));
            mc1 = fmaxf(mc1, fmaxf(s[nt][2], s[nt][3]));
        }
        mc0 = fmaxf(mc0, __shfl_xor_sync(0xffffffffu, mc0, 1));
        mc0 = fmaxf(mc0, __shfl_xor_sync(0xffffffffu, mc0, 2));
        mc1 = fmaxf(mc1, __shfl_xor_sync(0xffffffffu, mc1, 1));
        mc1 = fmaxf(mc1, __shfl_xor_sync(0xffffffffu, mc1, 2));

        const float mn0 = fmaxf(m0, mc0);
        const float mn1 = fmaxf(m1, mc1);
        const float cr0 = exp2f(m0 - mn0);
        const float cr1 = exp2f(m1 - mn1);
        m0 = mn0; m1 = mn1;

        float pl0 = 0.0f, pl1 = 0.0f;
        #pragma unroll
        for (int nt = 0; nt < 8; nt++) {
            const float p0 = exp2f(s[nt][0] - m0);
            const float p1 = exp2f(s[nt][1] - m0);
            const float p2 = exp2f(s[nt][2] - m1);
            const float p3 = exp2f(s[nt][3] - m1);
            pl0 += p0 + p1;
            pl1 += p2 + p3;
            const int col = nt * 8 + 2 * t;
            Ps[(qr + g)     * SQ + col]     = f2tf32(p0);
            Ps[(qr + g)     * SQ + col + 1] = f2tf32(p1);
            Ps[(qr + g + 8) * SQ + col]     = f2tf32(p2);
            Ps[(qr + g + 8) * SQ + col + 1] = f2tf32(p3);
        }
        pl0 += __shfl_xor_sync(0xffffffffu, pl0, 1);
        pl0 += __shfl_xor_sync(0xffffffffu, pl0, 2);
        pl1 += __shfl_xor_sync(0xffffffffu, pl1, 1);
        pl1 += __shfl_xor_sync(0xffffffffu, pl1, 2);

        l0 = l0 * cr0 + pl0;
        l1 = l1 * cr1 + pl1;
        #pragma unroll
        for (int n = 0; n < 8; n++) {
            O[n][0] *= cr0; O[n][1] *= cr0;
            O[n][2] *= cr1; O[n][3] *= cr1;
        }
        __syncwarp();   // P rows are warp-private; quad cross-reads below

        // O += P * V
        #pragma unroll
        for (int ks = 0; ks < 8; ks++) {
            const uint32_t a0 = Ps[(qr + g)     * SQ + ks * 8 + t];
            const uint32_t a1 = Ps[(qr + g + 8) * SQ + ks * 8 + t];
            const uint32_t a2 = Ps[(qr + g)     * SQ + ks * 8 + t + 4];
            const uint32_t a3 = Ps[(qr + g + 8) * SQ + ks * 8 + t + 4];
            #pragma unroll
            for (int nt2 = 0; nt2 < 8; nt2++) {
                const uint32_t b0 = Vs[(ks * 8 + t)     * SV + nt2 * 8 + g];
                const uint32_t b1 = Vs[(ks * 8 + t + 4) * SV + nt2 * 8 + g];
                mma_tf32(O[nt2], a0, a1, a2, a3, b0, b1);
            }
        }
    }

    // Epilogue: normalize, tf32-round (proj GEMM input), and store
    const float i0 = 1.0f / l0;
    const float i1 = 1.0f / l1;
    float* ya = y + ((size_t)b * T_SEQ + qa) * C_DIM + h * D_DIM;
    float* yb = y + ((size_t)b * T_SEQ + qb) * C_DIM + h * D_DIM;
    #pragma unroll
    for (int nt2 = 0; nt2 < 8; nt2++) {
        const int d = nt2 * 8 + 2 * t;
        *(float2*)(ya + d) = make_float2(
            __uint_as_float(f2tf32(O[nt2][0] * i0)),
            __uint_as_float(f2tf32(O[nt2][1] * i0)));
        *(float2*)(yb + d) = make_float2(
            __uint_as_float(f2tf32(O[nt2][2] * i1)),
            __uint_as_float(f2tf32(O[nt2][3] * i1)));
    }
}

// ---------------------------------------------------------------------------
// Launch
// ---------------------------------------------------------------------------
extern "C" void kernel_launch(void* const* d_in, const int* in_sizes, int n_in,
                              void* d_out, int out_size)
{
    const float* x      = (const float*)d_in[0];   // [8, 1024, 768]
    const float* W_attn = (const float*)d_in[1];   // [768, 2304]
    const float* b_attn = (const float*)d_in[2];   // [2304]
    const float* W_proj = (const float*)d_in[3];   // [768, 768]
    const float* b_proj = (const float*)d_in[4];   // [768]
    float* out = (float*)d_out;                    // [8, 1024, 768]

    float* qkv;  cudaGetSymbolAddress((void**)&qkv,  g_qkv);
    float* ybuf; cudaGetSymbolAddress((void**)&ybuf, g_y);
    float* xr;   cudaGetSymbolAddress((void**)&xr,   g_xr);
    float* WaT;  cudaGetSymbolAddress((void**)&WaT,  g_WarT);
    float* WpT;  cudaGetSymbolAddress((void**)&WpT,  g_WprT);

    cudaFuncSetAttribute(attn_mma_kernel,
                         cudaFuncAttributeMaxDynamicSharedMemorySize,
                         ATT_SMEM_BYTES);
    cudaFuncSetAttribute(gemm_tf32_bias_kernel<true>,
                         cudaFuncAttributeMaxDynamicSharedMemorySize,
                         GEMM_SMEM_BYTES);
    cudaFuncSetAttribute(gemm_tf32_bias_kernel<false>,
                         cudaFuncAttributeMaxDynamicSharedMemorySize,
                         GEMM_SMEM_BYTES);

    // 0) Pre-pass: round x; round+transpose weights into [N][K]
    {
        const int nx = M_ROWS * C_DIM / 4;
        round_tf32_kernel<<<(nx + 255) / 256, 256>>>(x, xr, nx);
        dim3 blk(32, 8);
        dim3 ga(N_QKV / 32, C_DIM / 32);    // (72, 24)
        round_transpose_tf32_kernel<<<ga, blk>>>(W_attn, WaT, C_DIM, N_QKV);
        dim3 gp(C_DIM / 32, C_DIM / 32);    // (24, 24)
        round_transpose_tf32_kernel<<<gp, blk>>>(W_proj, WpT, C_DIM, C_DIM);
    }
    // 1) QKV GEMM (ldmatrix operand path; output tf32-rounded)
    {
        dim3 grid(N_QKV / 128, M_ROWS / 128);   // (18, 64)
        gemm_tf32_bias_kernel<true><<<grid, 128, GEMM_SMEM_BYTES>>>(
            xr, WaT, b_attn, qkv, M_ROWS, N_QKV, C_DIM);
    }
    // 2) Causal flash attention (unchanged R14 structure)
    {
        dim3 grid(T_SEQ / 64, B_SZ * H_NUM);    // (16, 96)
        attn_mma_kernel<<<grid, 128, ATT_SMEM_BYTES>>>(qkv, ybuf);
    }
    // 3) Projection GEMM (ldmatrix operand path, full-fp32 output)
    {
        dim3 grid(C_DIM / 128, M_ROWS / 128);   // (6, 64)
        gemm_tf32_bias_kernel<false><<<grid, 128, GEMM_SMEM_BYTES>>>(
            ybuf, WpT, b_proj, out, M_ROWS, C_DIM, C_DIM);
    }
}